// round 7
// baseline (speedup 1.0000x reference)
#include <cuda_runtime.h>
#include <cstdint>

// Correlation: out[n,q,y,x] = (1/C) * sum_c d1[n,c,y,x] * d2pad[n,c,y+dy,x+dx]
// q = (dy+4)*9 + (dx+4). Shapes: N=8, C=256, H=96, W=160. Out (8,81,96,160) f32.
//
// R7: 8 px/thread + fma.rn.f32x2, 192-thread blocks, 3 CTAs/SM (18 warps),
// KC=4 double-buffered cp.async, b-pairs read as ulonglong2 (even pairs free).

#define CC   256
#define HH   96
#define WW   160
#define NN   8

constexpr int TX   = 32;   // tile width in pixels
constexpr int TTY  = 16;   // tile rows
constexpr int KC   = 4;    // channels per smem chunk
constexpr int S1S  = 36;   // s1 row stride (floats), 32 used
constexpr int S2S  = 44;   // s2 row stride (floats), 40 used
constexpr int S2R  = 18;   // s2 rows (16 + 2)
constexpr int NT   = 192;
constexpr int NCH  = CC / KC;               // 64 chunks
constexpr int S1_F = KC * TTY * S1S;        // 2304
constexpr int S2_F = KC * S2R * S2S;        // 3168
constexpr int STAGE_F = S1_F + S2_F;        // 5472
constexpr int SMEM_BYTES = 2 * STAGE_F * 4; // 43776 B

typedef unsigned long long u64;

__device__ __forceinline__ void cp16(uint32_t dst, const void* src, bool p) {
    asm volatile("cp.async.cg.shared.global [%0], [%1], 16, %2;\n"
                 :: "r"(dst), "l"(src), "r"(p ? 16 : 0));
}
__device__ __forceinline__ void cp_commit() {
    asm volatile("cp.async.commit_group;\n" ::: "memory");
}
template <int N>
__device__ __forceinline__ void cp_wait() {
    asm volatile("cp.async.wait_group %0;\n" :: "n"(N) : "memory");
}
__device__ __forceinline__ u64 pk(float lo, float hi) {
    u64 r;
    asm("mov.b64 %0, {%1, %2};" : "=l"(r) : "f"(lo), "f"(hi));
    return r;
}
__device__ __forceinline__ void upk(u64 v, float& lo, float& hi) {
    asm("mov.b64 {%0, %1}, %2;" : "=f"(lo), "=f"(hi) : "l"(v));
}
__device__ __forceinline__ void fma2(u64& acc, u64 a, u64 b) {
    asm("fma.rn.f32x2 %0, %1, %2, %0;" : "+l"(acc) : "l"(a), "l"(b));
}

__global__ __launch_bounds__(NT, 3)
void corr_kernel(const float* __restrict__ d1,
                 const float* __restrict__ d2,
                 float* __restrict__ out)
{
    extern __shared__ float smem[];

    // blockIdx.x = g3 + 3*tile_x ; blockIdx.y = tile_y + 6*n
    const int g3  = blockIdx.x % 3;
    const int tlx = blockIdx.x / 3;
    const int ty0 = (blockIdx.y % 6) * TTY;
    const int n   = blockIdx.y / 6;
    const int x0  = tlx * TX;

    const int t    = threadIdx.x;   // 0..191
    const int tsub = t / 64;        // dy within group
    const int tl   = t % 64;
    const int g    = tl % 4;        // x-group of 8 pixels
    const int tyl  = tl / 4;        // 0..15

    u64 acc[9][4];
#pragma unroll
    for (int dxi = 0; dxi < 9; dxi++)
#pragma unroll
        for (int p = 0; p < 4; p++) acc[dxi][p] = 0ull;

    const int dy_base = 3 * g3 - 4;
    const int yb      = ty0 + dy_base;
    const float* d1n = d1 + (size_t)n * CC * HH * WW;
    const float* d2n = d2 + (size_t)n * CC * HH * WW;

    const uint32_t smem_u32 = (uint32_t)__cvta_generic_to_shared(smem);

    // ---- per-thread copy slots (hoisted) ----
    // d1: threads 0..127 copy one float4 per channel.
    const bool ok1 = (t < 128);
    const int  yy1 = (t >> 3) & 15;
    const int  xg1 = t & 7;
    const float* s1p = d1n + (size_t)(ty0 + yy1) * WW + x0 + xg1 * 4;
    const uint32_t dst1 = (uint32_t)((yy1 * S1S + xg1 * 4) * 4);
    // d2: threads 0..179 copy one float4 per channel (zero-padded).
    const bool v2  = (t < 180);
    const int  rr2 = t / 10;
    const int  xg2 = t % 10;
    const int  gy2 = yb + rr2;
    const int  gx2 = x0 - 4 + xg2 * 4;
    const bool ok2 = v2 && gy2 >= 0 && gy2 < HH && gx2 >= 0 && gx2 + 3 < WW;
    const float* s2p = ok2 ? d2n + (size_t)gy2 * WW + gx2 : d2n;
    const uint32_t dst2 = (uint32_t)((rr2 * S2S + xg2 * 4) * 4);

    auto load_stage = [&](int stage) {
        const uint32_t sb  = smem_u32 + (uint32_t)(stage * STAGE_F * 4);
        const uint32_t s1b = sb + dst1;
        const uint32_t s2b = sb + (uint32_t)(S1_F * 4) + dst2;
#pragma unroll
        for (int cc = 0; cc < KC; cc++) {
            if (ok1) cp16(s1b + (uint32_t)(cc * TTY * S1S * 4), s1p, true);
            if (v2)  cp16(s2b + (uint32_t)(cc * S2R * S2S * 4), s2p, ok2);
            s1p += HH * WW;
            s2p += HH * WW;
        }
        cp_commit();
    };

    // ---- pipeline ----
    load_stage(0);

    int stage = 0;
    for (int it = 0; it < NCH; it++) {
        if (it + 1 < NCH) {
            load_stage(stage ^ 1);
            cp_wait<1>();
        } else {
            cp_wait<0>();
        }
        __syncthreads();

        const float* s1c = smem + stage * STAGE_F;
        const float* s2c = s1c + S1_F;

#pragma unroll
        for (int c = 0; c < KC; c++) {
            const float* arow = &s1c[(c * TTY + tyl) * S1S + g * 8];
            const ulonglong2 aA = *reinterpret_cast<const ulonglong2*>(arow);
            const ulonglong2 aB = *reinterpret_cast<const ulonglong2*>(arow + 4);
            const u64 ap[4] = {aA.x, aA.y, aB.x, aB.y};

            const float* brow = &s2c[(c * S2R + tyl + tsub) * S2S + g * 8];
            const ulonglong2 B0 = *reinterpret_cast<const ulonglong2*>(brow);
            const ulonglong2 B1 = *reinterpret_cast<const ulonglong2*>(brow + 4);
            const ulonglong2 B2 = *reinterpret_cast<const ulonglong2*>(brow + 8);
            const ulonglong2 B3 = *reinterpret_cast<const ulonglong2*>(brow + 12);
            // even f32x2 pairs are free register-pair views of the loads
            const u64 e[8] = {B0.x, B0.y, B1.x, B1.y, B2.x, B2.y, B3.x, B3.y};
            // odd pairs: (hi(e[k]), lo(e[k+1]))
            u64 o[7];
#pragma unroll
            for (int k = 0; k < 7; k++) {
                float l0, h0, l1, h1;
                upk(e[k], l0, h0);
                upk(e[k + 1], l1, h1);
                o[k] = pk(h0, l1);
            }
#pragma unroll
            for (int dxi = 0; dxi < 9; dxi++) {
#pragma unroll
                for (int p = 0; p < 4; p++) {
                    const int idx = 2 * p + dxi;
                    const u64 bb = (idx & 1) ? o[idx >> 1] : e[idx >> 1];
                    fma2(acc[dxi][p], ap[p], bb);
                }
            }
        }
        __syncthreads();
        stage ^= 1;
    }

    // ---- epilogue ----
    const float inv = 1.0f / (float)CC;
    const int y  = ty0 + tyl;
    const int xo = x0 + g * 8;
    const int dy = dy_base + tsub;
#pragma unroll
    for (int dxi = 0; dxi < 9; dxi++) {
        const int q = (dy + 4) * 9 + dxi;
        float o0[8];
#pragma unroll
        for (int p = 0; p < 4; p++) upk(acc[dxi][p], o0[2 * p], o0[2 * p + 1]);
        float* op = out + (((size_t)n * 81 + q) * HH + y) * WW + xo;
        *reinterpret_cast<float4*>(op) =
            make_float4(o0[0] * inv, o0[1] * inv, o0[2] * inv, o0[3] * inv);
        *reinterpret_cast<float4*>(op + 4) =
            make_float4(o0[4] * inv, o0[5] * inv, o0[6] * inv, o0[7] * inv);
    }
}

extern "C" void kernel_launch(void* const* d_in, const int* in_sizes, int n_in,
                              void* d_out, int out_size)
{
    const float* data1 = (const float*)d_in[0];
    const float* data2 = (const float*)d_in[1];
    float* out = (float*)d_out;

    cudaFuncSetAttribute(corr_kernel,
                         cudaFuncAttributeMaxDynamicSharedMemorySize,
                         SMEM_BYTES);

    dim3 grid(3 * (WW / TX), (HH / TTY) * NN, 1);  // (15, 48)
    dim3 block(NT, 1, 1);
    corr_kernel<<<grid, block, SMEM_BYTES>>>(data1, data2, out);
}